// round 16
// baseline (speedup 1.0000x reference)
#include <cuda_runtime.h>
#include <cuda_fp16.h>
#include <cstdint>

#define BB 64
#define NN 1024
#define DD 1024

// ---------------- device scratch (no allocations allowed) -------------------
__device__ float g_qh[BB * DD];
__device__ float g_scores[BB * NN];
__device__ __half g_keys_hi[(size_t)BB * NN * DD];
__device__ __half g_wk_hi[DD * DD];

__device__ __forceinline__ uint32_t smem_u32(const void* p) {
    uint32_t a;
    asm("{ .reg .u64 t; cvta.to.shared.u64 t, %1; cvt.u32.u64 %0, t; }"
        : "=r"(a) : "l"(p));
    return a;
}

__device__ __forceinline__ float tanh_fast(float x) {
    float y;
    asm("tanh.approx.f32 %0, %1;" : "=f"(y) : "f"(x));
    return y;
}

__device__ __forceinline__ void ldsm4(uint32_t* r, uint32_t addr) {
    asm volatile("ldmatrix.sync.aligned.m8n8.x4.shared.b16 {%0,%1,%2,%3}, [%4];"
                 : "=r"(r[0]), "=r"(r[1]), "=r"(r[2]), "=r"(r[3])
                 : "r"(addr));
}

__device__ __forceinline__ void hmma(float* c, const uint32_t* a,
                                     uint32_t b0, uint32_t b1) {
    asm volatile(
        "mma.sync.aligned.m16n8k16.row.col.f32.f16.f16.f32 "
        "{%0,%1,%2,%3}, {%4,%5,%6,%7}, {%8,%9}, {%0,%1,%2,%3};"
        : "+f"(c[0]), "+f"(c[1]), "+f"(c[2]), "+f"(c[3])
        : "r"(a[0]), "r"(a[1]), "r"(a[2]), "r"(a[3]), "r"(b0), "r"(b1));
}

__device__ __forceinline__ void cp_async16(uint32_t dst, const void* src) {
    asm volatile("cp.async.cg.shared.global [%0], [%1], 16;"
                 :: "r"(dst), "l"(src));
}
__device__ __forceinline__ void cp_commit() {
    asm volatile("cp.async.commit_group;");
}
template <int N>
__device__ __forceinline__ void cp_wait() {
    asm volatile("cp.async.wait_group %0;" :: "n"(N));
}

// ---------------------------------------------------------------------------
// split: f32 -> fp16
// ---------------------------------------------------------------------------
__global__ void split1_kernel(const float* __restrict__ src,
                              __half* __restrict__ hi) {
    size_t i = (size_t)blockIdx.x * 256 + threadIdx.x;
    float4 x = reinterpret_cast<const float4*>(src)[i];
    float f[4] = {x.x, x.y, x.z, x.w};
    __half h[4];
#pragma unroll
    for (int k = 0; k < 4; k++) h[k] = __float2half(f[k]);
    reinterpret_cast<uint2*>(hi)[i] = *reinterpret_cast<uint2*>(h);
}

// ---------------------------------------------------------------------------
// qh[b,e] = sum_d h[b,d] * Wh[e,d]
// grid 128, block 256 (warp per e, 8 e's/CTA). Wh row held in registers
// (read ONCE from DRAM); h staged through a 32KB smem buffer, 8 batches
// per iteration x 8 iterations.
// ---------------------------------------------------------------------------
__global__ void qh_kernel(const float* __restrict__ h,
                          const float* __restrict__ Wh) {
    __shared__ float hsf[8 * DD];        // 8 batches x 4KB = 32KB
    const int tid = threadIdx.x;
    const int wid = tid >> 5;
    const int lane = tid & 31;
    const int e = blockIdx.x * 8 + wid;

    // Wh[e] into 32 regs per lane: w[j] = Wh[e][j*32+lane]
    float w[32];
    const float* wr = Wh + (size_t)e * DD;
#pragma unroll
    for (int j = 0; j < 32; j++) w[j] = wr[j * 32 + lane];

    for (int grp = 0; grp < 8; grp++) {
        __syncthreads();
        // stage 8 batches of h into smem (8 * 1024 floats = 2048 float4s)
        for (int i = tid; i < 8 * DD / 4; i += 256) {
            float4 x = reinterpret_cast<const float4*>(
                h + (size_t)(grp * 8) * DD)[i];
            reinterpret_cast<float4*>(hsf)[i] = x;
        }
        __syncthreads();

#pragma unroll
        for (int bb = 0; bb < 8; bb++) {
            const float* hb = hsf + bb * DD;
            float acc = 0.f;
#pragma unroll
            for (int j = 0; j < 32; j++)
                acc += w[j] * hb[j * 32 + lane];
#pragma unroll
            for (int off = 16; off > 0; off >>= 1)
                acc += __shfl_xor_sync(0xffffffffu, acc, off);
            if (lane == 0) g_qh[(grp * 8 + bb) * DD + e] = acc;
        }
    }
}

// ---------------------------------------------------------------------------
// Fused scores kernel (HMMA mma.sync), single fp16 term:
//   kh = keys_fp16 @ Wk_fp16   (fp32 accumulate)
// CTA = (b, 128-n tile). 8 e-passes of 128; flat chunk loop with
// single-sync double buffering:  wait -> sync -> stage(next) -> compute.
// (R10-measured structure.)
// ---------------------------------------------------------------------------
#define TILE_BYTES 16384                 // 128 x 64 halves
#define STAGE_BYTES (2 * TILE_BYTES)     // A + B
#define OFF_QS (2 * STAGE_BYTES)         // 65536
#define OFF_VS (OFF_QS + 512)
#define OFF_RED (OFF_VS + 512)
#define SMEM_TOTAL (OFF_RED + 1024)

// swizzled byte offset inside a 128x(64 half) tile: row, 16B-group c8 (0..7)
__device__ __forceinline__ uint32_t swz(int row, int c8) {
    return (uint32_t)(row * 128 + ((c8 ^ (row & 7)) << 4));
}

__global__ __launch_bounds__(256, 2)
void scores_mma_kernel(const float* __restrict__ v) {
    extern __shared__ char sm[];
    const uint32_t sbase = smem_u32(sm);
    const int tid = threadIdx.x;
    const int wid = tid >> 5;
    const int lane = tid & 31;
    const int b = blockIdx.x;
    const int n0 = blockIdx.y * 128;

    const int wn = wid & 3;   // n-warp (0..3), 32 rows each
    const int we = wid >> 2;  // e-warp (0..1), 64 cols each

    float* qs = reinterpret_cast<float*>(sm + OFF_QS);
    float* vs = reinterpret_cast<float*>(sm + OFF_VS);
    float* red = reinterpret_cast<float*>(sm + OFF_RED);

    const __half* keyb = g_keys_hi + ((size_t)b * NN + n0) * DD;

    // staging indices: thread covers (row, c8) pairs
    const int st_row = tid >> 3;       // 0..31 (+32 steps)
    const int st_c8 = tid & 7;

    // ldmatrix lane addressing
    const int a_row = lane & 15;
    const int a_sel = lane >> 4;       // 16B group within k16 (0/1)
    const int b_g = lane & 7;
    const int b_sel = lane >> 3;
    const int b_row = b_g + ((b_sel >> 1) << 3);
    const int b_c8s = b_sel & 1;       // 16B group within k16

    // stage chunk (sep = e-pass, sc = k-chunk) into buffer buf
    auto stage = [&](int sep, int sc, int buf) {
        const int k0 = sc * 64;
        const uint32_t base = sbase + (uint32_t)buf * STAGE_BYTES;
        const __half* wk = g_wk_hi + (size_t)(sep * 128) * DD;
#pragma unroll
        for (int it = 0; it < 4; it++) {
            int row = st_row + it * 32;
            uint32_t off = swz(row, st_c8);
            const size_t g = (size_t)row * DD + k0 + st_c8 * 8;
            cp_async16(base + off, keyb + g);
            cp_async16(base + TILE_BYTES + off, wk + g);
        }
    };

    float C[2][8][4];
#pragma unroll
    for (int m = 0; m < 2; m++)
#pragma unroll
        for (int nf = 0; nf < 8; nf++)
#pragma unroll
            for (int r = 0; r < 4; r++) C[m][nf][r] = 0.f;
    float sacc[4] = {0.f, 0.f, 0.f, 0.f};

    // prologue: stage (0,0) into buf 0
    stage(0, 0, 0);
    cp_commit();
    int gbuf = 0;   // parity of the chunk being computed

    for (int ep = 0; ep < 8; ep++) {
        if (tid < 128) {
            qs[tid] = g_qh[b * DD + ep * 128 + tid];
            vs[tid] = v[ep * 128 + tid];
        }

        for (int c = 0; c < 16; c++) {
            cp_wait<0>();
            __syncthreads();

            // stage the next chunk (possibly chunk 0 of the next pass)
            if (!(ep == 7 && c == 15)) {
                int ne = (c == 15) ? ep + 1 : ep;
                int nc = (c == 15) ? 0 : c + 1;
                stage(ne, nc, gbuf ^ 1);
                cp_commit();
            }

            const uint32_t bufA = sbase + (uint32_t)gbuf * STAGE_BYTES;
            const uint32_t bufB = bufA + TILE_BYTES;
#pragma unroll
            for (int kk = 0; kk < 4; kk++) {
                uint32_t a[2][4];
#pragma unroll
                for (int m = 0; m < 2; m++) {
                    int row = wn * 32 + m * 16 + a_row;
                    ldsm4(a[m], bufA + swz(row, kk * 2 + a_sel));
                }
                uint32_t bf[4][4];
#pragma unroll
                for (int q = 0; q < 4; q++) {
                    int row = we * 64 + q * 16 + b_row;
                    ldsm4(bf[q], bufB + swz(row, kk * 2 + b_c8s));
                }
#pragma unroll
                for (int m = 0; m < 2; m++)
#pragma unroll
                    for (int nf = 0; nf < 8; nf++)
                        hmma(C[m][nf], a[m],
                             bf[nf >> 1][(nf & 1) * 2],
                             bf[nf >> 1][(nf & 1) * 2 + 1]);
            }
            gbuf ^= 1;
        }

        // epilogue: sacc += v * tanh(qh + C); zero C for next pass
#pragma unroll
        for (int m = 0; m < 2; m++)
#pragma unroll
            for (int nf = 0; nf < 8; nf++) {
                float* c = C[m][nf];
                int ec = we * 64 + nf * 8 + ((lane & 3) << 1);
                float q0 = qs[ec], q1 = qs[ec + 1];
                float v0 = vs[ec], v1 = vs[ec + 1];
                sacc[m * 2 + 0] += v0 * tanh_fast(q0 + c[0]) +
                                   v1 * tanh_fast(q1 + c[1]);
                sacc[m * 2 + 1] += v0 * tanh_fast(q0 + c[2]) +
                                   v1 * tanh_fast(q1 + c[3]);
                c[0] = c[1] = c[2] = c[3] = 0.f;
            }
        __syncthreads();   // qs/vs safe to overwrite next pass
    }

    // reduce sacc over the 4-lane k-groups (same rows)
#pragma unroll
    for (int i = 0; i < 4; i++) {
        sacc[i] += __shfl_xor_sync(0xffffffffu, sacc[i], 1);
        sacc[i] += __shfl_xor_sync(0xffffffffu, sacc[i], 2);
    }
    if ((lane & 3) == 0) {
        int g = lane >> 2;
        float* r = red + we * 128 + wn * 32;
        r[g]      = sacc[0];
        r[g + 8]  = sacc[1];
        r[g + 16] = sacc[2];
        r[g + 24] = sacc[3];
    }
    __syncthreads();
    if (tid < 128)
        g_scores[b * NN + n0 + tid] = red[tid] + red[128 + tid];
}

// ---------------------------------------------------------------------------
// softmax over N per row; writes alpha into d_out[B*D ...]
// ---------------------------------------------------------------------------
__global__ void softmax_kernel(float* __restrict__ out) {
    __shared__ float sx[NN];
    __shared__ float red[256];
    const int b = blockIdx.x;
    const int tid = threadIdx.x;
    const float* s = &g_scores[b * NN];

    float m = -1e30f;
    for (int i = tid; i < NN; i += 256) {
        float val = s[i];
        sx[i] = val;
        m = fmaxf(m, val);
    }
    red[tid] = m;
    __syncthreads();
    for (int off = 128; off > 0; off >>= 1) {
        if (tid < off) red[tid] = fmaxf(red[tid], red[tid + off]);
        __syncthreads();
    }
    const float M = red[0];
    __syncthreads();

    float sum = 0.f;
    for (int i = tid; i < NN; i += 256) {
        float e = __expf(sx[i] - M);
        sx[i] = e;
        sum += e;
    }
    red[tid] = sum;
    __syncthreads();
    for (int off = 128; off > 0; off >>= 1) {
        if (tid < off) red[tid] += red[tid + off];
        __syncthreads();
    }
    const float inv = 1.f / red[0];
    __syncthreads();

    float* alpha = out + (size_t)BB * DD + (size_t)b * NN;
    for (int i = tid; i < NN; i += 256)
        alpha[i] = sx[i] * inv;
}

// ---------------------------------------------------------------------------
// context[b,d] = sum_n alpha[b,n] * keys_fp16[b,n,d]
// grid (B, 4), block 256, thread per d; fp16 keys (half the DRAM traffic).
// ---------------------------------------------------------------------------
__global__ void context_kernel(float* __restrict__ out) {
    __shared__ float al[NN];
    const int b = blockIdx.x;
    const int d = blockIdx.y * 256 + threadIdx.x;
    const float* alpha = out + (size_t)BB * DD + (size_t)b * NN;
    for (int i = threadIdx.x; i < NN; i += 256) al[i] = alpha[i];
    __syncthreads();

    const __half* kb = g_keys_hi + (size_t)b * NN * DD + d;
    float acc0 = 0.f, acc1 = 0.f, acc2 = 0.f, acc3 = 0.f;
#pragma unroll 4
    for (int n = 0; n < NN; n += 4) {
        acc0 += al[n + 0] * __half2float(kb[(size_t)(n + 0) * DD]);
        acc1 += al[n + 1] * __half2float(kb[(size_t)(n + 1) * DD]);
        acc2 += al[n + 2] * __half2float(kb[(size_t)(n + 2) * DD]);
        acc3 += al[n + 3] * __half2float(kb[(size_t)(n + 3) * DD]);
    }
    out[(size_t)b * DD + d] = (acc0 + acc1) + (acc2 + acc3);
}

// ---------------------------------------------------------------------------
extern "C" void kernel_launch(void* const* d_in, const int* in_sizes, int n_in,
                              void* d_out, int out_size) {
    const float* h_t  = (const float*)d_in[0];
    const float* keys = (const float*)d_in[1];
    const float* W_h  = (const float*)d_in[2];
    const float* W_k  = (const float*)d_in[3];
    const float* v    = (const float*)d_in[4];
    float* out = (float*)d_out;

    cudaFuncSetAttribute(scores_mma_kernel,
                         cudaFuncAttributeMaxDynamicSharedMemorySize, SMEM_TOTAL);

    __half *khi, *whi;
    cudaGetSymbolAddress((void**)&khi, g_keys_hi);
    cudaGetSymbolAddress((void**)&whi, g_wk_hi);

    split1_kernel<<<(size_t)BB * NN * DD / 4 / 256, 256>>>(keys, khi);
    split1_kernel<<<DD * DD / 4 / 256, 256>>>(W_k, whi);
    qh_kernel<<<DD / 8, 256>>>(h_t, W_h);
    scores_mma_kernel<<<dim3(BB, 8), 256, SMEM_TOTAL>>>(v);
    softmax_kernel<<<BB, 256>>>(out);
    context_kernel<<<dim3(BB, 4), 256>>>(out);
}

// round 17
// speedup vs baseline: 1.0808x; 1.0808x over previous
#include <cuda_runtime.h>
#include <cuda_fp16.h>
#include <cstdint>

#define BB 64
#define NN 1024
#define DD 1024

// scores work decomposition: unit = (tile, ep); tile = b*8 + ntile
#define GRID_SC 304              // 2 CTAs/SM x 152 SMs (GB300)
#define NUNITS 4096              // 512 tiles x 8 e-passes

// ---------------- device scratch (no allocations allowed) -------------------
__device__ float g_qh[BB * DD];
__device__ float g_spart[8 * BB * NN];   // per-ep partial scores
__device__ __half g_keys_hi[(size_t)BB * NN * DD];
__device__ __half g_wk_hi[DD * DD];

__device__ __forceinline__ uint32_t smem_u32(const void* p) {
    uint32_t a;
    asm("{ .reg .u64 t; cvta.to.shared.u64 t, %1; cvt.u32.u64 %0, t; }"
        : "=r"(a) : "l"(p));
    return a;
}

__device__ __forceinline__ float tanh_fast(float x) {
    float y;
    asm("tanh.approx.f32 %0, %1;" : "=f"(y) : "f"(x));
    return y;
}

__device__ __forceinline__ void ldsm4(uint32_t* r, uint32_t addr) {
    asm volatile("ldmatrix.sync.aligned.m8n8.x4.shared.b16 {%0,%1,%2,%3}, [%4];"
                 : "=r"(r[0]), "=r"(r[1]), "=r"(r[2]), "=r"(r[3])
                 : "r"(addr));
}

__device__ __forceinline__ void hmma(float* c, const uint32_t* a,
                                     uint32_t b0, uint32_t b1) {
    asm volatile(
        "mma.sync.aligned.m16n8k16.row.col.f32.f16.f16.f32 "
        "{%0,%1,%2,%3}, {%4,%5,%6,%7}, {%8,%9}, {%0,%1,%2,%3};"
        : "+f"(c[0]), "+f"(c[1]), "+f"(c[2]), "+f"(c[3])
        : "r"(a[0]), "r"(a[1]), "r"(a[2]), "r"(a[3]), "r"(b0), "r"(b1));
}

__device__ __forceinline__ void cp_async16(uint32_t dst, const void* src) {
    asm volatile("cp.async.cg.shared.global [%0], [%1], 16;"
                 :: "r"(dst), "l"(src));
}
__device__ __forceinline__ void cp_commit() {
    asm volatile("cp.async.commit_group;");
}
template <int N>
__device__ __forceinline__ void cp_wait() {
    asm volatile("cp.async.wait_group %0;" :: "n"(N));
}

// ---------------------------------------------------------------------------
// split: f32 -> fp16
// ---------------------------------------------------------------------------
__global__ void split1_kernel(const float* __restrict__ src,
                              __half* __restrict__ hi) {
    size_t i = (size_t)blockIdx.x * 256 + threadIdx.x;
    float4 x = reinterpret_cast<const float4*>(src)[i];
    float f[4] = {x.x, x.y, x.z, x.w};
    __half h[4];
#pragma unroll
    for (int k = 0; k < 4; k++) h[k] = __float2half(f[k]);
    reinterpret_cast<uint2*>(hi)[i] = *reinterpret_cast<uint2*>(h);
}

// ---------------------------------------------------------------------------
// qh[b,e] = sum_d h[b,d] * Wh[e,d]
// grid 128, block 256 (warp per e). Wh row in registers; h via 32KB smem.
// ---------------------------------------------------------------------------
__global__ void qh_kernel(const float* __restrict__ h,
                          const float* __restrict__ Wh) {
    __shared__ float hsf[8 * DD];        // 8 batches x 4KB = 32KB
    const int tid = threadIdx.x;
    const int wid = tid >> 5;
    const int lane = tid & 31;
    const int e = blockIdx.x * 8 + wid;

    float w[32];
    const float* wr = Wh + (size_t)e * DD;
#pragma unroll
    for (int j = 0; j < 32; j++) w[j] = wr[j * 32 + lane];

    for (int grp = 0; grp < 8; grp++) {
        __syncthreads();
        for (int i = tid; i < 8 * DD / 4; i += 256) {
            float4 x = reinterpret_cast<const float4*>(
                h + (size_t)(grp * 8) * DD)[i];
            reinterpret_cast<float4*>(hsf)[i] = x;
        }
        __syncthreads();

#pragma unroll
        for (int bb = 0; bb < 8; bb++) {
            const float* hb = hsf + bb * DD;
            float acc = 0.f;
#pragma unroll
            for (int j = 0; j < 32; j++)
                acc += w[j] * hb[j * 32 + lane];
#pragma unroll
            for (int off = 16; off > 0; off >>= 1)
                acc += __shfl_xor_sync(0xffffffffu, acc, off);
            if (lane == 0) g_qh[(grp * 8 + bb) * DD + e] = acc;
        }
    }
}

// ---------------------------------------------------------------------------
// Persistent fused scores kernel (HMMA), unit = (tile, ep).
// 304 CTAs; CTA processes units uid = bid, bid+304, ...  (ep = bid&7 is
// CONSTANT per CTA -> its Wk slice stays L2-hot). Double-buffered cp.async
// pipeline carried across unit boundaries. Per unit: 16 k-chunks of 64,
// then epilogue writes 128 partial scores to g_spart[ep][b][n-tile].
// ---------------------------------------------------------------------------
#define TILE_BYTES 16384                 // 128 x 64 halves
#define STAGE_BYTES (2 * TILE_BYTES)     // A + B
#define OFF_QS (2 * STAGE_BYTES)         // 65536
#define OFF_VS (OFF_QS + 512)
#define OFF_RED (OFF_VS + 512)
#define SMEM_TOTAL (OFF_RED + 1024)

// swizzled byte offset inside a 128x(64 half) tile: row, 16B-group c8 (0..7)
__device__ __forceinline__ uint32_t swz(int row, int c8) {
    return (uint32_t)(row * 128 + ((c8 ^ (row & 7)) << 4));
}

__global__ __launch_bounds__(256, 2)
void scores_mma_kernel(const float* __restrict__ v) {
    extern __shared__ char sm[];
    const uint32_t sbase = smem_u32(sm);
    const int tid = threadIdx.x;
    const int wid = tid >> 5;
    const int lane = tid & 31;
    const int bid = blockIdx.x;

    const int wn = wid & 3;   // n-warp (0..3), 32 rows each
    const int we = wid >> 2;  // e-warp (0..1), 64 cols each

    float* qs = reinterpret_cast<float*>(sm + OFF_QS);
    float* vs = reinterpret_cast<float*>(sm + OFF_VS);
    float* red = reinterpret_cast<float*>(sm + OFF_RED);

    // number of units for this CTA; flat chunk count
    const int nu = (NUNITS - bid + GRID_SC - 1) / GRID_SC;
    const int jmax = nu * 16;

    // ep is constant per CTA (GRID_SC % 8 == 0)
    const int ep = bid & 7;
    const __half* wk = g_wk_hi + (size_t)(ep * 128) * DD;

    // staging indices
    const int st_row = tid >> 3;       // 0..31 (+32 steps)
    const int st_c8 = tid & 7;

    // ldmatrix lane addressing
    const int a_row = lane & 15;
    const int a_sel = lane >> 4;
    const int b_g = lane & 7;
    const int b_sel = lane >> 3;
    const int b_row = b_g + ((b_sel >> 1) << 3);
    const int b_c8s = b_sel & 1;

    // stage flat chunk j into buffer (j&1)
    auto stage = [&](int j) {
        const int uid = bid + (j >> 4) * GRID_SC;
        const int tile = uid >> 3;                      // = b*8 + ntile
        const int c = j & 15;
        const int k0 = c * 64;
        const uint32_t base = sbase + (uint32_t)(j & 1) * STAGE_BYTES;
        const __half* keyb = g_keys_hi + (size_t)tile * 128 * DD;
#pragma unroll
        for (int it = 0; it < 4; it++) {
            int row = st_row + it * 32;
            uint32_t off = swz(row, st_c8);
            const size_t g = (size_t)row * DD + k0 + st_c8 * 8;
            cp_async16(base + off, keyb + g);
            cp_async16(base + TILE_BYTES + off, wk + g);
        }
    };

    float C[2][8][4];
#pragma unroll
    for (int m = 0; m < 2; m++)
#pragma unroll
        for (int nf = 0; nf < 8; nf++)
#pragma unroll
            for (int r = 0; r < 4; r++) C[m][nf][r] = 0.f;

    stage(0);
    cp_commit();

    for (int j = 0; j < jmax; j++) {
        cp_wait<0>();
        __syncthreads();

        const int c = j & 15;
        const int uid = bid + (j >> 4) * GRID_SC;
        const int tile = uid >> 3;

        if (c == 0 && tid < 128) {
            // qh slice for this unit's (b, ep); v slice for ep
            int b = tile >> 3;
            qs[tid] = g_qh[b * DD + ep * 128 + tid];
            vs[tid] = v[ep * 128 + tid];
        }

        if (j + 1 < jmax) {
            stage(j + 1);
            cp_commit();
        }

        const uint32_t bufA = sbase + (uint32_t)(j & 1) * STAGE_BYTES;
        const uint32_t bufB = bufA + TILE_BYTES;
#pragma unroll
        for (int kk = 0; kk < 4; kk++) {
            uint32_t a[2][4];
#pragma unroll
            for (int m = 0; m < 2; m++) {
                int row = wn * 32 + m * 16 + a_row;
                ldsm4(a[m], bufA + swz(row, kk * 2 + a_sel));
            }
            uint32_t bf[4][4];
#pragma unroll
            for (int q = 0; q < 4; q++) {
                int row = we * 64 + q * 16 + b_row;
                ldsm4(bf[q], bufB + swz(row, kk * 2 + b_c8s));
            }
#pragma unroll
            for (int m = 0; m < 2; m++)
#pragma unroll
                for (int nf = 0; nf < 8; nf++)
                    hmma(C[m][nf], a[m],
                         bf[nf >> 1][(nf & 1) * 2],
                         bf[nf >> 1][(nf & 1) * 2 + 1]);
        }

        if (c == 15) {
            // epilogue: partial score for this unit; write to g_spart
            float sacc[4] = {0.f, 0.f, 0.f, 0.f};
#pragma unroll
            for (int m = 0; m < 2; m++)
#pragma unroll
                for (int nf = 0; nf < 8; nf++) {
                    float* cc = C[m][nf];
                    int ec = we * 64 + nf * 8 + ((lane & 3) << 1);
                    float q0 = qs[ec], q1 = qs[ec + 1];
                    float v0 = vs[ec], v1 = vs[ec + 1];
                    sacc[m * 2 + 0] += v0 * tanh_fast(q0 + cc[0]) +
                                       v1 * tanh_fast(q1 + cc[1]);
                    sacc[m * 2 + 1] += v0 * tanh_fast(q0 + cc[2]) +
                                       v1 * tanh_fast(q1 + cc[3]);
                    cc[0] = cc[1] = cc[2] = cc[3] = 0.f;
                }
#pragma unroll
            for (int i = 0; i < 4; i++) {
                sacc[i] += __shfl_xor_sync(0xffffffffu, sacc[i], 1);
                sacc[i] += __shfl_xor_sync(0xffffffffu, sacc[i], 2);
            }
            if ((lane & 3) == 0) {
                int g = lane >> 2;
                float* r = red + we * 128 + wn * 32;
                r[g]      = sacc[0];
                r[g + 8]  = sacc[1];
                r[g + 16] = sacc[2];
                r[g + 24] = sacc[3];
            }
            __syncthreads();
            if (tid < 128) {
                int b = tile >> 3;
                int n0 = (tile & 7) * 128;
                g_spart[(size_t)ep * BB * NN + b * NN + n0 + tid] =
                    red[tid] + red[128 + tid];
            }
        }
    }
}

// ---------------------------------------------------------------------------
// softmax: sum the 8 per-ep partials, then softmax; alpha -> d_out[B*D ...]
// ---------------------------------------------------------------------------
__global__ void softmax_kernel(float* __restrict__ out) {
    __shared__ float sx[NN];
    __shared__ float red[256];
    const int b = blockIdx.x;
    const int tid = threadIdx.x;

    float m = -1e30f;
    for (int i = tid; i < NN; i += 256) {
        float val = 0.f;
#pragma unroll
        for (int e = 0; e < 8; e++)
            val += g_spart[(size_t)e * BB * NN + b * NN + i];
        sx[i] = val;
        m = fmaxf(m, val);
    }
    red[tid] = m;
    __syncthreads();
    for (int off = 128; off > 0; off >>= 1) {
        if (tid < off) red[tid] = fmaxf(red[tid], red[tid + off]);
        __syncthreads();
    }
    const float M = red[0];
    __syncthreads();

    float sum = 0.f;
    for (int i = tid; i < NN; i += 256) {
        float e = __expf(sx[i] - M);
        sx[i] = e;
        sum += e;
    }
    red[tid] = sum;
    __syncthreads();
    for (int off = 128; off > 0; off >>= 1) {
        if (tid < off) red[tid] += red[tid + off];
        __syncthreads();
    }
    const float inv = 1.f / red[0];
    __syncthreads();

    float* alpha = out + (size_t)BB * DD + (size_t)b * NN;
    for (int i = tid; i < NN; i += 256)
        alpha[i] = sx[i] * inv;
}

// ---------------------------------------------------------------------------
// context[b,d] = sum_n alpha[b,n] * keys_fp16[b,n,d]
// grid (B, 4), block 256, thread per d; fp16 keys.
// ---------------------------------------------------------------------------
__global__ void context_kernel(float* __restrict__ out) {
    __shared__ float al[NN];
    const int b = blockIdx.x;
    const int d = blockIdx.y * 256 + threadIdx.x;
    const float* alpha = out + (size_t)BB * DD + (size_t)b * NN;
    for (int i = threadIdx.x; i < NN; i += 256) al[i] = alpha[i];
    __syncthreads();

    const __half* kb = g_keys_hi + (size_t)b * NN * DD + d;
    float acc0 = 0.f, acc1 = 0.f, acc2 = 0.f, acc3 = 0.f;
#pragma unroll 4
    for (int n = 0; n < NN; n += 4) {
        acc0 += al[n + 0] * __half2float(kb[(size_t)(n + 0) * DD]);
        acc1 += al[n + 1] * __half2float(kb[(size_t)(n + 1) * DD]);
        acc2 += al[n + 2] * __half2float(kb[(size_t)(n + 2) * DD]);
        acc3 += al[n + 3] * __half2float(kb[(size_t)(n + 3) * DD]);
    }
    out[(size_t)b * DD + d] = (acc0 + acc1) + (acc2 + acc3);
}

// ---------------------------------------------------------------------------
extern "C" void kernel_launch(void* const* d_in, const int* in_sizes, int n_in,
                              void* d_out, int out_size) {
    const float* h_t  = (const float*)d_in[0];
    const float* keys = (const float*)d_in[1];
    const float* W_h  = (const float*)d_in[2];
    const float* W_k  = (const float*)d_in[3];
    const float* v    = (const float*)d_in[4];
    float* out = (float*)d_out;

    cudaFuncSetAttribute(scores_mma_kernel,
                         cudaFuncAttributeMaxDynamicSharedMemorySize, SMEM_TOTAL);

    __half *khi, *whi;
    cudaGetSymbolAddress((void**)&khi, g_keys_hi);
    cudaGetSymbolAddress((void**)&whi, g_wk_hi);

    split1_kernel<<<(size_t)BB * NN * DD / 4 / 256, 256>>>(keys, khi);
    split1_kernel<<<DD * DD / 4 / 256, 256>>>(W_k, whi);
    qh_kernel<<<DD / 8, 256>>>(h_t, W_h);
    scores_mma_kernel<<<GRID_SC, 256, SMEM_TOTAL>>>(v);
    softmax_kernel<<<BB, 256>>>(out);
    context_kernel<<<dim3(BB, 4), 256>>>(out);
}